// round 9
// baseline (speedup 1.0000x reference)
#include <cuda_runtime.h>

typedef unsigned long long ull;

// ---------------- packed f32x2 helpers (Blackwell) ----------------
__device__ __forceinline__ ull bc2(float f) {
    ull r; asm("mov.b64 %0, {%1, %1};" : "=l"(r) : "f"(f)); return r;
}
__device__ __forceinline__ ull pk2(float a, float b) {
    ull r; asm("mov.b64 %0, {%1, %2};" : "=l"(r) : "f"(a), "f"(b)); return r;
}
__device__ __forceinline__ float2 up2(ull u) {
    float2 v; asm("mov.b64 {%0, %1}, %2;" : "=f"(v.x), "=f"(v.y) : "l"(u)); return v;
}
__device__ __forceinline__ ull mul2(ull a, ull b) {
    ull r; asm("mul.rn.f32x2 %0, %1, %2;" : "=l"(r) : "l"(a), "l"(b)); return r;
}
__device__ __forceinline__ ull fma2(ull a, ull b, ull c) {
    ull r; asm("fma.rn.f32x2 %0, %1, %2, %3;" : "=l"(r) : "l"(a), "l"(b), "l"(c)); return r;
}
__device__ __forceinline__ ull add2(ull a, ull b) {
    ull r; asm("add.rn.f32x2 %0, %1, %2;" : "=l"(r) : "l"(a), "l"(b)); return r;
}

// cp.async 16B: global -> shared
__device__ __forceinline__ void cpa16(void* dst_smem, const void* src) {
    unsigned sa = (unsigned)__cvta_generic_to_shared(dst_smem);
    asm volatile("cp.async.cg.shared.global [%0], [%1], 16;" :: "r"(sa), "l"(src));
}

// q-index into a stage's [512][2][2] twiddle table for element pair (p, p+s).
__device__ __forceinline__ int qidx(int p, int ls) {
    int s = 1 << ls;
    return ((p >> (ls + 1)) << ls) | (p & (s - 1));
}

// Transpose-buffer padding (1/32): both access patterns conflict-free for
// 64-bit LDS/STS (verified by enumeration mod 32).
__device__ __forceinline__ int phys(int p) { return p + (p >> 5); }

static const int NGROUPS_TOTAL = 8192;   // 32768 rows / 4 per group
static const int GRID = 444;             // 148 SMs x 3 CTAs

// dynamic smem layout (per CTA, 65792 B total -> 3 CTAs/SM = 197 KB < 228 KB):
//   [0,     8448)  transpose buf: 1056 float2 (one row-pair, 2-pass)
//   [8448, 33024)  twA table: [3][4][128] float4 (phase-A twiddles)
//   [33024,65792)  input staging: 2 buffers x 4 rows x 256 float4
static const int BUF_OFF = 0;
static const int TWA_OFF = 8448;
static const int XIN_OFF = 33024;
static const int SMEM_DYN = 65792;

// ---------------- persistent main kernel ----------------
// 3 CTAs/SM (12 warps) x 128 threads. Register budget <=170:
//   tB(64) + tC(48) in registers; tA via per-block smem table (self-indexed,
//   no barrier); bias reloaded per use (__ldg, L1-hit). Double-buffered
//   cp.async input prefetch.
__global__ void __launch_bounds__(128, 3) butterfly_main(
    const float* __restrict__ x,
    const float* __restrict__ tw,       // [10][512][2][2]
    const float* __restrict__ bias,
    float* __restrict__ out)
{
    extern __shared__ char smem_raw[];
    float2* buf  = reinterpret_cast<float2*>(smem_raw + BUF_OFF);
    float4* twA  = reinterpret_cast<float4*>(smem_raw + TWA_OFF);
    float4* xin  = reinterpret_cast<float4*>(smem_raw + XIN_OFF);

    const int t = threadIdx.x;
    const float4* tw4 = reinterpret_cast<const float4*>(tw);  // [10][512] float4

    // ---- build phase-A twiddle table in smem (each thread writes & later
    // reads ONLY its own 12 entries -> no barrier needed) ----
    #pragma unroll
    for (int ls = 0; ls < 3; ls++) {
        const int s = 1 << ls;
        #pragma unroll
        for (int j = 0; j < 4; j++) {
            int eL = ((j >> ls) << (ls + 1)) | (j & (s - 1));
            twA[(ls * 4 + j) * 128 + t] = tw4[ls * 512 + qidx(8 * t + eL, ls)];
        }
    }

    // ---- phase-B + phase-C twiddles in registers (112 floats) ----
    float tB[4][4][4];   // [ls-3][j][ta0,tb0,ta1,tb1]
    float tC[3][4][4];   // [ls-7][j][t00,t01,t10,t11]

    #pragma unroll
    for (int ls = 3; ls < 7; ls++) {
        const int i = (t >> (ls - 3)) & 1;
        #pragma unroll
        for (int j = 0; j < 4; j++) {
            float4 w0 = tw4[ls * 512 + qidx(8 * t + 2 * j,     ls)];
            float4 w1 = tw4[ls * 512 + qidx(8 * t + 2 * j + 1, ls)];
            // role 0: out = t00*own + t01*other ; role 1: out = t11*own + t10*other
            tB[ls-3][j][0] = i ? w0.w : w0.x;
            tB[ls-3][j][1] = i ? w0.z : w0.y;
            tB[ls-3][j][2] = i ? w1.w : w1.x;
            tB[ls-3][j][3] = i ? w1.z : w1.y;
        }
    }
    #pragma unroll
    for (int ls = 7; ls < 10; ls++) {
        const int sig = 1 << (ls - 7);
        #pragma unroll
        for (int j = 0; j < 4; j++) {
            int eL = ((j >> (ls - 7)) << (ls - 7 + 1)) | (j & (sig - 1));
            float4 w = tw4[ls * 512 + qidx(t + 128 * eL, ls)];
            tC[ls-7][j][0] = w.x; tC[ls-7][j][1] = w.y; tC[ls-7][j][2] = w.z; tC[ls-7][j][3] = w.w;
        }
    }

    // ---- staging: group gg -> buffer b ----
    auto stage = [&](int gg, int b) {
        if (gg < NGROUPS_TOTAL) {
            #pragma unroll
            for (int r = 0; r < 4; r++) {
                const float* src = x + (size_t)(gg * 4 + r) * 1024 + 8 * t;
                float4* dst = &xin[(b * 4 + r) * 256 + 2 * t];
                cpa16(dst, src);
                cpa16(dst + 1, src + 4);
            }
        }
        asm volatile("cp.async.commit_group;");
    };

    const int g0 = blockIdx.x;
    stage(g0, 0);

    int par = 0;
    for (int g = g0; g < NGROUPS_TOTAL; g += GRID) {
        // prefetch next group into other buffer, then wait for current
        stage(g + GRID, par ^ 1);
        asm volatile("cp.async.wait_group 1;");

        // read this group's input (self-staged -> no barrier)
        ull D[2][8];
        #pragma unroll
        for (int c = 0; c < 2; c++) {
            const float4* s0 = &xin[(par * 4 + 2 * c    ) * 256 + 2 * t];
            const float4* s1 = &xin[(par * 4 + 2 * c + 1) * 256 + 2 * t];
            float4 a0 = s0[0], a1 = s0[1];
            float4 b0 = s1[0], b1 = s1[1];
            D[c][0] = pk2(a0.x, b0.x);  D[c][1] = pk2(a0.y, b0.y);
            D[c][2] = pk2(a0.z, b0.z);  D[c][3] = pk2(a0.w, b0.w);
            D[c][4] = pk2(a1.x, b1.x);  D[c][5] = pk2(a1.y, b1.y);
            D[c][6] = pk2(a1.z, b1.z);  D[c][7] = pk2(a1.w, b1.w);
        }
        par ^= 1;

        // phase A: strides 1,2,4 (intra-thread), twiddles from smem table
        #pragma unroll
        for (int ls = 0; ls < 3; ls++) {
            const int s = 1 << ls;
            #pragma unroll
            for (int j = 0; j < 4; j++) {
                float4 w = twA[(ls * 4 + j) * 128 + t];
                const int eL = ((j >> ls) << (ls + 1)) | (j & (s - 1));
                const int eH = eL + s;
                ull t00 = bc2(w.x), t01 = bc2(w.y), t10 = bc2(w.z), t11 = bc2(w.w);
                #pragma unroll
                for (int c = 0; c < 2; c++) {
                    ull x0 = D[c][eL], x1 = D[c][eH];
                    D[c][eL] = fma2(t00, x0, mul2(t01, x1));
                    D[c][eH] = fma2(t10, x0, mul2(t11, x1));
                }
            }
        }

        // phase B: strides 8,16,32,64 via warp shuffles (lane xor 1,2,4,8)
        #pragma unroll
        for (int ls = 3; ls < 7; ls++) {
            const int k = 1 << (ls - 3);
            #pragma unroll
            for (int j = 0; j < 4; j++) {
                ull ta0 = bc2(tB[ls-3][j][0]), tb0 = bc2(tB[ls-3][j][1]);
                ull ta1 = bc2(tB[ls-3][j][2]), tb1 = bc2(tB[ls-3][j][3]);
                const int e0 = 2 * j, e1 = 2 * j + 1;
                #pragma unroll
                for (int c = 0; c < 2; c++) {
                    ull o0 = __shfl_xor_sync(0xffffffffu, D[c][e0], k);
                    D[c][e0] = fma2(ta0, D[c][e0], mul2(tb0, o0));
                    ull o1 = __shfl_xor_sync(0xffffffffu, D[c][e1], k);
                    D[c][e1] = fma2(ta1, D[c][e1], mul2(tb1, o1));
                }
            }
        }

        // per row-pair: 2-pass transpose + phase C + epilogue
        #pragma unroll
        for (int c = 0; c < 2; c++) {
            __syncthreads();   // previous pass's readers done with buf
            #pragma unroll
            for (int e = 0; e < 8; e++) {
                int p = 8 * t + e;
                buf[phys(p)] = up2(D[c][e]);
            }
            __syncthreads();
            #pragma unroll
            for (int e = 0; e < 8; e++) {
                int p = t + 128 * e;
                float2 v = buf[phys(p)];
                D[c][e] = pk2(v.x, v.y);
            }

            // phase C: strides 128,256,512 (intra-thread in e)
            #pragma unroll
            for (int ls = 7; ls < 10; ls++) {
                const int sig = 1 << (ls - 7);
                #pragma unroll
                for (int j = 0; j < 4; j++) {
                    const int eL = ((j >> (ls - 7)) << (ls - 7 + 1)) | (j & (sig - 1));
                    const int eH = eL + sig;
                    ull t00 = bc2(tC[ls-7][j][0]), t01 = bc2(tC[ls-7][j][1]);
                    ull t10 = bc2(tC[ls-7][j][2]), t11 = bc2(tC[ls-7][j][3]);
                    ull x0 = D[c][eL], x1 = D[c][eH];
                    D[c][eL] = fma2(t00, x0, mul2(t01, x1));
                    D[c][eH] = fma2(t10, x0, mul2(t11, x1));
                }
            }

            // epilogue: bias (__ldg, L1-hit) + coalesced streaming stores
            float* o0 = out + (size_t)(g * 4 + 2 * c    ) * 1024;
            float* o1 = out + (size_t)(g * 4 + 2 * c + 1) * 1024;
            #pragma unroll
            for (int e = 0; e < 8; e++) {
                int p = t + 128 * e;
                float2 v = up2(add2(D[c][e], bc2(__ldg(&bias[p]))));
                __stcs(o0 + p, v.x);
                __stcs(o1 + p, v.y);
            }
        }
    }
}

extern "C" void kernel_launch(void* const* d_in, const int* in_sizes, int n_in,
                              void* d_out, int out_size) {
    const float* x    = (const float*)d_in[0];   // [32768, 1024]
    const float* tw   = (const float*)d_in[1];   // [1,1,10,512,2,2]
    const float* bias = (const float*)d_in[2];   // [1024]
    float* out = (float*)d_out;

    cudaFuncSetAttribute(butterfly_main,
                         cudaFuncAttributeMaxDynamicSharedMemorySize, SMEM_DYN);
    butterfly_main<<<GRID, 128, SMEM_DYN>>>(x, tw, bias, out);
}

// round 10
// speedup vs baseline: 1.1083x; 1.1083x over previous
#include <cuda_runtime.h>

typedef unsigned long long ull;

// ---------------- packed f32x2 helpers (Blackwell) ----------------
__device__ __forceinline__ ull bc2(float f) {
    ull r; asm("mov.b64 %0, {%1, %1};" : "=l"(r) : "f"(f)); return r;
}
__device__ __forceinline__ ull pk2(float a, float b) {
    ull r; asm("mov.b64 %0, {%1, %2};" : "=l"(r) : "f"(a), "f"(b)); return r;
}
__device__ __forceinline__ float2 up2(ull u) {
    float2 v; asm("mov.b64 {%0, %1}, %2;" : "=f"(v.x), "=f"(v.y) : "l"(u)); return v;
}
__device__ __forceinline__ ull mul2(ull a, ull b) {
    ull r; asm("mul.rn.f32x2 %0, %1, %2;" : "=l"(r) : "l"(a), "l"(b)); return r;
}
__device__ __forceinline__ ull fma2(ull a, ull b, ull c) {
    ull r; asm("fma.rn.f32x2 %0, %1, %2, %3;" : "=l"(r) : "l"(a), "l"(b), "l"(c)); return r;
}
__device__ __forceinline__ ull add2(ull a, ull b) {
    ull r; asm("add.rn.f32x2 %0, %1, %2;" : "=l"(r) : "l"(a), "l"(b)); return r;
}

// cp.async 16B: global -> shared
__device__ __forceinline__ void cpa16(void* dst_smem, const void* src) {
    unsigned sa = (unsigned)__cvta_generic_to_shared(dst_smem);
    asm volatile("cp.async.cg.shared.global [%0], [%1], 16;" :: "r"(sa), "l"(src));
}

// q-index into a stage's [512][2][2] twiddle table for element pair (p, p+s).
__device__ __forceinline__ int qidx(int p, int ls) {
    int s = 1 << ls;
    return ((p >> (ls + 1)) << ls) | (p & (s - 1));
}

// Transpose-buffer padding (1/32): store side p=8t+e and read side p=t+128e
// both conflict-free for 64-bit accesses (verified by enumeration mod 32).
__device__ __forceinline__ int phys(int p) { return p + (p >> 5); }

static const int NGROUPS_TOTAL = 8192;   // 32768 rows / 4 per group (C=2 row-pairs)
static const int GRID = 296;             // 148 SMs x 2 CTAs

// dynamic smem layout (82944 B/CTA; 2 CTAs/SM = 166 KB < 228 KB):
//   [0,     33792)  transpose buf, DOUBLE buffered: [2][2 row-pairs][1056] float2
//   [33792, 82944)  input staging: 3 buffers x 4 rows x 256 float4
static const int BUF_F2   = 1056;                   // float2 per row-pair
static const int BUF_ITER = 2 * BUF_F2;             // 2112 float2 per iteration
static const int XIN_OFF  = 2 * BUF_ITER * 8;       // 33792
static const int SMEM_DYN = XIN_OFF + 3 * 4 * 1024 * 4;   // 82944

// ---------------- persistent main kernel ----------------
// Block = 128 threads; each iteration = 4 rows (2 packed row-pairs).
// Twiddles register-cached once per block. Triple-buffered cp.async input
// prefetch (distance 2). Double-buffered transpose -> ONE barrier/iter:
// with alternating buffers, iter i+1's STS never races iter i-1's LDS
// (LDS_{i-1} precedes every thread's arrival at barrier_i; STS_{i+1}
// follows it), so the old end-of-loop barrier is redundant and removed.
__global__ void __launch_bounds__(128, 2) butterfly_main(
    const float* __restrict__ x,
    const float* __restrict__ tw,       // [10][512][2][2]
    const float* __restrict__ bias,
    float* __restrict__ out)
{
    extern __shared__ char smem_raw[];
    float2* buf = reinterpret_cast<float2*>(smem_raw);                 // [2][2][1056]
    float4* xin = reinterpret_cast<float4*>(smem_raw + XIN_OFF);       // [3][4][256]

    const int t = threadIdx.x;
    const float4* tw4 = reinterpret_cast<const float4*>(tw);  // [10][512] float4

    // ---- one-time twiddle load + repack into registers (160 floats) ----
    float tA[3][4][4];   // phase A: [ls][j][t00,t01,t10,t11]
    float tB[4][4][4];   // phase B: [ls-3][j][ta0,tb0,ta1,tb1]
    float tC[3][4][4];   // phase C: [ls-7][j][t00,t01,t10,t11]

    #pragma unroll
    for (int ls = 0; ls < 3; ls++) {
        const int s = 1 << ls;
        #pragma unroll
        for (int j = 0; j < 4; j++) {
            int eL = ((j >> ls) << (ls + 1)) | (j & (s - 1));
            float4 w = tw4[ls * 512 + qidx(8 * t + eL, ls)];
            tA[ls][j][0] = w.x; tA[ls][j][1] = w.y; tA[ls][j][2] = w.z; tA[ls][j][3] = w.w;
        }
    }
    #pragma unroll
    for (int ls = 3; ls < 7; ls++) {
        const int i = (t >> (ls - 3)) & 1;
        #pragma unroll
        for (int j = 0; j < 4; j++) {
            float4 w0 = tw4[ls * 512 + qidx(8 * t + 2 * j,     ls)];
            float4 w1 = tw4[ls * 512 + qidx(8 * t + 2 * j + 1, ls)];
            // role 0: out = t00*own + t01*other ; role 1: out = t11*own + t10*other
            tB[ls-3][j][0] = i ? w0.w : w0.x;
            tB[ls-3][j][1] = i ? w0.z : w0.y;
            tB[ls-3][j][2] = i ? w1.w : w1.x;
            tB[ls-3][j][3] = i ? w1.z : w1.y;
        }
    }
    #pragma unroll
    for (int ls = 7; ls < 10; ls++) {
        const int sig = 1 << (ls - 7);
        #pragma unroll
        for (int j = 0; j < 4; j++) {
            int eL = ((j >> (ls - 7)) << (ls - 7 + 1)) | (j & (sig - 1));
            float4 w = tw4[ls * 512 + qidx(t + 128 * eL, ls)];
            tC[ls-7][j][0] = w.x; tC[ls-7][j][1] = w.y; tC[ls-7][j][2] = w.z; tC[ls-7][j][3] = w.w;
        }
    }

    // packed bias for phase-C ownership p = t + 128e
    ull bv2[8];
    #pragma unroll
    for (int e = 0; e < 8; e++) bv2[e] = bc2(bias[t + 128 * e]);

    // ---- staging helper: stage group gg into buffer b ----
    auto stage = [&](int gg, int b) {
        if (gg < NGROUPS_TOTAL) {
            #pragma unroll
            for (int r = 0; r < 4; r++) {
                const float* src = x + (size_t)(gg * 4 + r) * 1024 + 8 * t;
                float4* dst = &xin[(b * 4 + r) * 256 + 2 * t];
                cpa16(dst, src);
                cpa16(dst + 1, src + 4);
            }
        }
        asm volatile("cp.async.commit_group;");
    };

    // ---- prologue: stage first two groups (prefetch distance 2) ----
    const int g0 = blockIdx.x;
    stage(g0, 0);
    stage(g0 + GRID, 1);

    int par = 0;   // staging ring position
    int db  = 0;   // transpose double-buffer parity
    for (int g = g0; g < NGROUPS_TOTAL; g += GRID) {
        // stage group g+2*GRID into the third buffer (overlaps compute)
        int nb = par + 2; if (nb >= 3) nb -= 3;
        stage(g + 2 * GRID, nb);
        asm volatile("cp.async.wait_group 2;");   // buffer par landed

        // read this group's input from smem (self-staged -> no barrier)
        ull D[2][8];
        #pragma unroll
        for (int c = 0; c < 2; c++) {
            const float4* s0 = &xin[(par * 4 + 2 * c    ) * 256 + 2 * t];
            const float4* s1 = &xin[(par * 4 + 2 * c + 1) * 256 + 2 * t];
            float4 a0 = s0[0], a1 = s0[1];
            float4 b0 = s1[0], b1 = s1[1];
            D[c][0] = pk2(a0.x, b0.x);  D[c][1] = pk2(a0.y, b0.y);
            D[c][2] = pk2(a0.z, b0.z);  D[c][3] = pk2(a0.w, b0.w);
            D[c][4] = pk2(a1.x, b1.x);  D[c][5] = pk2(a1.y, b1.y);
            D[c][6] = pk2(a1.z, b1.z);  D[c][7] = pk2(a1.w, b1.w);
        }
        if (++par >= 3) par = 0;

        // phase A: strides 1,2,4 (intra-thread)
        #pragma unroll
        for (int ls = 0; ls < 3; ls++) {
            const int s = 1 << ls;
            #pragma unroll
            for (int j = 0; j < 4; j++) {
                const int eL = ((j >> ls) << (ls + 1)) | (j & (s - 1));
                const int eH = eL + s;
                ull t00 = bc2(tA[ls][j][0]), t01 = bc2(tA[ls][j][1]);
                ull t10 = bc2(tA[ls][j][2]), t11 = bc2(tA[ls][j][3]);
                #pragma unroll
                for (int c = 0; c < 2; c++) {
                    ull x0 = D[c][eL], x1 = D[c][eH];
                    D[c][eL] = fma2(t00, x0, mul2(t01, x1));
                    D[c][eH] = fma2(t10, x0, mul2(t11, x1));
                }
            }
        }

        // phase B: strides 8,16,32,64 via warp shuffles (lane xor 1,2,4,8)
        #pragma unroll
        for (int ls = 3; ls < 7; ls++) {
            const int k = 1 << (ls - 3);
            #pragma unroll
            for (int j = 0; j < 4; j++) {
                ull ta0 = bc2(tB[ls-3][j][0]), tb0 = bc2(tB[ls-3][j][1]);
                ull ta1 = bc2(tB[ls-3][j][2]), tb1 = bc2(tB[ls-3][j][3]);
                const int e0 = 2 * j, e1 = 2 * j + 1;
                #pragma unroll
                for (int c = 0; c < 2; c++) {
                    ull o0 = __shfl_xor_sync(0xffffffffu, D[c][e0], k);
                    D[c][e0] = fma2(ta0, D[c][e0], mul2(tb0, o0));
                    ull o1 = __shfl_xor_sync(0xffffffffu, D[c][e1], k);
                    D[c][e1] = fma2(ta1, D[c][e1], mul2(tb1, o1));
                }
            }
        }

        // ownership transpose through shared (single pass, double-buffered)
        float2* tb = buf + db * BUF_ITER;
        #pragma unroll
        for (int c = 0; c < 2; c++)
            #pragma unroll
            for (int e = 0; e < 8; e++) {
                int p = 8 * t + e;
                tb[c * BUF_F2 + phys(p)] = up2(D[c][e]);
            }
        __syncthreads();                       // the ONLY barrier per iteration
        #pragma unroll
        for (int c = 0; c < 2; c++)
            #pragma unroll
            for (int e = 0; e < 8; e++) {
                int p = t + 128 * e;
                float2 v = tb[c * BUF_F2 + phys(p)];
                D[c][e] = pk2(v.x, v.y);
            }
        db ^= 1;

        // phase C: strides 128,256,512 (intra-thread in e)
        #pragma unroll
        for (int ls = 7; ls < 10; ls++) {
            const int sig = 1 << (ls - 7);
            #pragma unroll
            for (int j = 0; j < 4; j++) {
                const int eL = ((j >> (ls - 7)) << (ls - 7 + 1)) | (j & (sig - 1));
                const int eH = eL + sig;
                ull t00 = bc2(tC[ls-7][j][0]), t01 = bc2(tC[ls-7][j][1]);
                ull t10 = bc2(tC[ls-7][j][2]), t11 = bc2(tC[ls-7][j][3]);
                #pragma unroll
                for (int c = 0; c < 2; c++) {
                    ull x0 = D[c][eL], x1 = D[c][eH];
                    D[c][eL] = fma2(t00, x0, mul2(t01, x1));
                    D[c][eH] = fma2(t10, x0, mul2(t11, x1));
                }
            }
        }

        // epilogue: packed bias add + coalesced streaming stores
        #pragma unroll
        for (int c = 0; c < 2; c++) {
            float* o0 = out + (size_t)(g * 4 + 2 * c    ) * 1024;
            float* o1 = out + (size_t)(g * 4 + 2 * c + 1) * 1024;
            #pragma unroll
            for (int e = 0; e < 8; e++) {
                float2 v = up2(add2(D[c][e], bv2[e]));
                int p = t + 128 * e;
                __stcs(o0 + p, v.x);
                __stcs(o1 + p, v.y);
            }
        }
    }
}

extern "C" void kernel_launch(void* const* d_in, const int* in_sizes, int n_in,
                              void* d_out, int out_size) {
    const float* x    = (const float*)d_in[0];   // [32768, 1024]
    const float* tw   = (const float*)d_in[1];   // [1,1,10,512,2,2]
    const float* bias = (const float*)d_in[2];   // [1024]
    float* out = (float*)d_out;

    cudaFuncSetAttribute(butterfly_main,
                         cudaFuncAttributeMaxDynamicSharedMemorySize, SMEM_DYN);
    butterfly_main<<<GRID, 128, SMEM_DYN>>>(x, tw, bias, out);
}

// round 11
// speedup vs baseline: 1.2187x; 1.0997x over previous
#include <cuda_runtime.h>

typedef unsigned long long ull;

// ---------------- packed f32x2 helpers (Blackwell) ----------------
__device__ __forceinline__ ull bc2(float f) {
    ull r; asm("mov.b64 %0, {%1, %1};" : "=l"(r) : "f"(f)); return r;
}
__device__ __forceinline__ ull pk2(float a, float b) {
    ull r; asm("mov.b64 %0, {%1, %2};" : "=l"(r) : "f"(a), "f"(b)); return r;
}
__device__ __forceinline__ float2 up2(ull u) {
    float2 v; asm("mov.b64 {%0, %1}, %2;" : "=f"(v.x), "=f"(v.y) : "l"(u)); return v;
}
__device__ __forceinline__ ull mul2(ull a, ull b) {
    ull r; asm("mul.rn.f32x2 %0, %1, %2;" : "=l"(r) : "l"(a), "l"(b)); return r;
}
__device__ __forceinline__ ull fma2(ull a, ull b, ull c) {
    ull r; asm("fma.rn.f32x2 %0, %1, %2, %3;" : "=l"(r) : "l"(a), "l"(b), "l"(c)); return r;
}
__device__ __forceinline__ ull add2(ull a, ull b) {
    ull r; asm("add.rn.f32x2 %0, %1, %2;" : "=l"(r) : "l"(a), "l"(b)); return r;
}

// cp.async 16B: global -> shared
__device__ __forceinline__ void cpa16(void* dst_smem, const void* src) {
    unsigned sa = (unsigned)__cvta_generic_to_shared(dst_smem);
    asm volatile("cp.async.cg.shared.global [%0], [%1], 16;" :: "r"(sa), "l"(src));
}

// q-index into a stage's [512][2][2] twiddle table for element pair (p, p+s).
__device__ __forceinline__ int qidx(int p, int ls) {
    int s = 1 << ls;
    return ((p >> (ls + 1)) << ls) | (p & (s - 1));
}

// Transpose padding 1/8: verified conflict-free (mod-16 enumeration) for
// store p=8t+e, O2 pattern p=(t&7)|(e<<3)|((t>>3)<<6) (both sides), and
// read p=t+128e (single 2-way slot -> negligible).
__device__ __forceinline__ int phys(int p) { return p + (p >> 3); }

// O2 ownership: element index for thread t, slot e.
__device__ __forceinline__ int o2p(int t, int e) {
    return (t & 7) | (e << 3) | ((t >> 3) << 6);
}

static const int NGROUPS_TOTAL = 8192;   // 32768 rows / 4 per group (2 row-pairs)
static const int GRID = 296;             // 148 SMs x 2 CTAs

// dynamic smem layout (86016 B/CTA; 2 CTAs/SM = 168 KB < 228 KB):
//   [0,     36864)  two transpose buffers: [2][2 row-pairs][1152] float2
//   [36864, 86016)  input staging: 3 buffers x 4 rows x 256 float4
static const int BUF_F2   = 1152;                   // float2 per row-pair
static const int BUF_ONE  = 2 * BUF_F2;             // one transpose buffer (2 c)
static const int XIN_OFF  = 2 * BUF_ONE * 8;        // 36864
static const int SMEM_DYN = XIN_OFF + 3 * 4 * 1024 * 4;   // 86016

// ---------------- persistent main kernel ----------------
// Stage schedule (R11): O1 intra(1,2,4) -> T1 -> O2 intra(8,16,32) ->
// ONE shfl stage (64, lane^8) -> T2 -> O3 intra(128,256,512).
// Cuts 128 SHFL.32/iter to 32 at the cost of +32 LDS/STS (net -64 MIO ops)
// and collapses the 4-deep shfl dependency chain to 1.
__global__ void __launch_bounds__(128, 2) butterfly_main(
    const float* __restrict__ x,
    const float* __restrict__ tw,       // [10][512][2][2]
    const float* __restrict__ bias,
    float* __restrict__ out)
{
    extern __shared__ char smem_raw[];
    float2* bufT1 = reinterpret_cast<float2*>(smem_raw);               // [2][1152]
    float2* bufT2 = bufT1 + BUF_ONE;                                   // [2][1152]
    float4* xin   = reinterpret_cast<float4*>(smem_raw + XIN_OFF);     // [3][4][256]

    const int t = threadIdx.x;
    const float4* tw4 = reinterpret_cast<const float4*>(tw);  // [10][512] float4

    // ---- one-time twiddle load + repack into registers (160 floats) ----
    float tA[3][4][4];   // O1 stages 1,2,4:    [ls][j][t00,t01,t10,t11]
    float tB[3][4][4];   // O2 stages 8,16,32:  [ls-3][j][t00,t01,t10,t11]
    float tS[8][2];      // shfl stage 64:      [e][ta,tb]
    float tC[3][4][4];   // O3 stages 128..512: [ls-7][j][t00,t01,t10,t11]

    #pragma unroll
    for (int ls = 0; ls < 3; ls++) {
        const int s = 1 << ls;
        #pragma unroll
        for (int j = 0; j < 4; j++) {
            int eL = ((j >> ls) << (ls + 1)) | (j & (s - 1));
            float4 w = tw4[ls * 512 + qidx(8 * t + eL, ls)];
            tA[ls][j][0] = w.x; tA[ls][j][1] = w.y; tA[ls][j][2] = w.z; tA[ls][j][3] = w.w;
        }
    }
    #pragma unroll
    for (int ls = 3; ls < 6; ls++) {
        const int sig = 1 << (ls - 3);
        #pragma unroll
        for (int j = 0; j < 4; j++) {
            int eL = ((j >> (ls - 3)) << (ls - 3 + 1)) | (j & (sig - 1));
            float4 w = tw4[ls * 512 + qidx(o2p(t, eL), ls)];
            tB[ls-3][j][0] = w.x; tB[ls-3][j][1] = w.y; tB[ls-3][j][2] = w.z; tB[ls-3][j][3] = w.w;
        }
    }
    {
        const int i = (t >> 3) & 1;   // bit 6 of o2p = bit 3 of t
        #pragma unroll
        for (int e = 0; e < 8; e++) {
            float4 w = tw4[6 * 512 + qidx(o2p(t, e), 6)];
            // role 0: out = t00*own + t01*other ; role 1: out = t11*own + t10*other
            tS[e][0] = i ? w.w : w.x;
            tS[e][1] = i ? w.z : w.y;
        }
    }
    #pragma unroll
    for (int ls = 7; ls < 10; ls++) {
        const int sig = 1 << (ls - 7);
        #pragma unroll
        for (int j = 0; j < 4; j++) {
            int eL = ((j >> (ls - 7)) << (ls - 7 + 1)) | (j & (sig - 1));
            float4 w = tw4[ls * 512 + qidx(t + 128 * eL, ls)];
            tC[ls-7][j][0] = w.x; tC[ls-7][j][1] = w.y; tC[ls-7][j][2] = w.z; tC[ls-7][j][3] = w.w;
        }
    }

    // packed bias for O3 ownership p = t + 128e
    ull bv2[8];
    #pragma unroll
    for (int e = 0; e < 8; e++) bv2[e] = bc2(bias[t + 128 * e]);

    // ---- staging helper: stage group gg into buffer b ----
    auto stage = [&](int gg, int b) {
        if (gg < NGROUPS_TOTAL) {
            #pragma unroll
            for (int r = 0; r < 4; r++) {
                const float* src = x + (size_t)(gg * 4 + r) * 1024 + 8 * t;
                float4* dst = &xin[(b * 4 + r) * 256 + 2 * t];
                cpa16(dst, src);
                cpa16(dst + 1, src + 4);
            }
        }
        asm volatile("cp.async.commit_group;");
    };

    // ---- prologue: stage first two groups (prefetch distance 2) ----
    const int g0 = blockIdx.x;
    stage(g0, 0);
    stage(g0 + GRID, 1);

    int par = 0;
    for (int g = g0; g < NGROUPS_TOTAL; g += GRID) {
        int nb = par + 2; if (nb >= 3) nb -= 3;
        stage(g + 2 * GRID, nb);
        asm volatile("cp.async.wait_group 2;");   // buffer par landed

        // input read from staging (self-staged -> no barrier); O1 ownership
        ull D[2][8];
        #pragma unroll
        for (int c = 0; c < 2; c++) {
            const float4* s0 = &xin[(par * 4 + 2 * c    ) * 256 + 2 * t];
            const float4* s1 = &xin[(par * 4 + 2 * c + 1) * 256 + 2 * t];
            float4 a0 = s0[0], a1 = s0[1];
            float4 b0 = s1[0], b1 = s1[1];
            D[c][0] = pk2(a0.x, b0.x);  D[c][1] = pk2(a0.y, b0.y);
            D[c][2] = pk2(a0.z, b0.z);  D[c][3] = pk2(a0.w, b0.w);
            D[c][4] = pk2(a1.x, b1.x);  D[c][5] = pk2(a1.y, b1.y);
            D[c][6] = pk2(a1.z, b1.z);  D[c][7] = pk2(a1.w, b1.w);
        }
        if (++par >= 3) par = 0;

        // O1: stages 1,2,4 (intra-thread, e bits 0-2)
        #pragma unroll
        for (int ls = 0; ls < 3; ls++) {
            const int s = 1 << ls;
            #pragma unroll
            for (int j = 0; j < 4; j++) {
                const int eL = ((j >> ls) << (ls + 1)) | (j & (s - 1));
                const int eH = eL + s;
                ull t00 = bc2(tA[ls][j][0]), t01 = bc2(tA[ls][j][1]);
                ull t10 = bc2(tA[ls][j][2]), t11 = bc2(tA[ls][j][3]);
                #pragma unroll
                for (int c = 0; c < 2; c++) {
                    ull x0 = D[c][eL], x1 = D[c][eH];
                    D[c][eL] = fma2(t00, x0, mul2(t01, x1));
                    D[c][eH] = fma2(t10, x0, mul2(t11, x1));
                }
            }
        }

        // ---- transpose 1: O1 (p=8t+e) -> O2 ----
        #pragma unroll
        for (int c = 0; c < 2; c++)
            #pragma unroll
            for (int e = 0; e < 8; e++) {
                int p = 8 * t + e;
                bufT1[c * BUF_F2 + phys(p)] = up2(D[c][e]);
            }
        __syncthreads();
        #pragma unroll
        for (int c = 0; c < 2; c++)
            #pragma unroll
            for (int e = 0; e < 8; e++) {
                float2 v = bufT1[c * BUF_F2 + phys(o2p(t, e))];
                D[c][e] = pk2(v.x, v.y);
            }

        // O2: stages 8,16,32 (intra-thread, e bits = p bits 3-5)
        #pragma unroll
        for (int ls = 3; ls < 6; ls++) {
            const int sig = 1 << (ls - 3);
            #pragma unroll
            for (int j = 0; j < 4; j++) {
                const int eL = ((j >> (ls - 3)) << (ls - 3 + 1)) | (j & (sig - 1));
                const int eH = eL + sig;
                ull t00 = bc2(tB[ls-3][j][0]), t01 = bc2(tB[ls-3][j][1]);
                ull t10 = bc2(tB[ls-3][j][2]), t11 = bc2(tB[ls-3][j][3]);
                #pragma unroll
                for (int c = 0; c < 2; c++) {
                    ull x0 = D[c][eL], x1 = D[c][eH];
                    D[c][eL] = fma2(t00, x0, mul2(t01, x1));
                    D[c][eH] = fma2(t10, x0, mul2(t11, x1));
                }
            }
        }

        // stage 64: ONE shfl stage (p bit 6 = t bit 3 -> lane^8)
        #pragma unroll
        for (int c = 0; c < 2; c++)
            #pragma unroll
            for (int e = 0; e < 8; e++) {
                ull o = __shfl_xor_sync(0xffffffffu, D[c][e], 8);
                D[c][e] = fma2(bc2(tS[e][0]), D[c][e], mul2(bc2(tS[e][1]), o));
            }

        // ---- transpose 2: O2 -> O3 (p = t + 128e) ----
        #pragma unroll
        for (int c = 0; c < 2; c++)
            #pragma unroll
            for (int e = 0; e < 8; e++) {
                bufT2[c * BUF_F2 + phys(o2p(t, e))] = up2(D[c][e]);
            }
        __syncthreads();
        #pragma unroll
        for (int c = 0; c < 2; c++)
            #pragma unroll
            for (int e = 0; e < 8; e++) {
                float2 v = bufT2[c * BUF_F2 + phys(t + 128 * e)];
                D[c][e] = pk2(v.x, v.y);
            }

        // O3: stages 128,256,512 (intra-thread, e bits = p bits 7-9)
        #pragma unroll
        for (int ls = 7; ls < 10; ls++) {
            const int sig = 1 << (ls - 7);
            #pragma unroll
            for (int j = 0; j < 4; j++) {
                const int eL = ((j >> (ls - 7)) << (ls - 7 + 1)) | (j & (sig - 1));
                const int eH = eL + sig;
                ull t00 = bc2(tC[ls-7][j][0]), t01 = bc2(tC[ls-7][j][1]);
                ull t10 = bc2(tC[ls-7][j][2]), t11 = bc2(tC[ls-7][j][3]);
                #pragma unroll
                for (int c = 0; c < 2; c++) {
                    ull x0 = D[c][eL], x1 = D[c][eH];
                    D[c][eL] = fma2(t00, x0, mul2(t01, x1));
                    D[c][eH] = fma2(t10, x0, mul2(t11, x1));
                }
            }
        }

        // epilogue: packed bias add + coalesced streaming stores
        #pragma unroll
        for (int c = 0; c < 2; c++) {
            float* o0 = out + (size_t)(g * 4 + 2 * c    ) * 1024;
            float* o1 = out + (size_t)(g * 4 + 2 * c + 1) * 1024;
            #pragma unroll
            for (int e = 0; e < 8; e++) {
                float2 v = up2(add2(D[c][e], bv2[e]));
                int p = t + 128 * e;
                __stcs(o0 + p, v.x);
                __stcs(o1 + p, v.y);
            }
        }
    }
}

extern "C" void kernel_launch(void* const* d_in, const int* in_sizes, int n_in,
                              void* d_out, int out_size) {
    const float* x    = (const float*)d_in[0];   // [32768, 1024]
    const float* tw   = (const float*)d_in[1];   // [1,1,10,512,2,2]
    const float* bias = (const float*)d_in[2];   // [1024]
    float* out = (float*)d_out;

    cudaFuncSetAttribute(butterfly_main,
                         cudaFuncAttributeMaxDynamicSharedMemorySize, SMEM_DYN);
    butterfly_main<<<GRID, 128, SMEM_DYN>>>(x, tw, bias, out);
}

// round 13
// speedup vs baseline: 1.3569x; 1.1134x over previous
#include <cuda_runtime.h>

typedef unsigned long long ull;

// ---------------- packed f32x2 helpers (Blackwell) ----------------
__device__ __forceinline__ ull bc2(float f) {
    ull r; asm("mov.b64 %0, {%1, %1};" : "=l"(r) : "f"(f)); return r;
}
__device__ __forceinline__ ull pk2(float a, float b) {
    ull r; asm("mov.b64 %0, {%1, %2};" : "=l"(r) : "f"(a), "f"(b)); return r;
}
__device__ __forceinline__ float2 up2(ull u) {
    float2 v; asm("mov.b64 {%0, %1}, %2;" : "=f"(v.x), "=f"(v.y) : "l"(u)); return v;
}
__device__ __forceinline__ ull mul2(ull a, ull b) {
    ull r; asm("mul.rn.f32x2 %0, %1, %2;" : "=l"(r) : "l"(a), "l"(b)); return r;
}
__device__ __forceinline__ ull fma2(ull a, ull b, ull c) {
    ull r; asm("fma.rn.f32x2 %0, %1, %2, %3;" : "=l"(r) : "l"(a), "l"(b), "l"(c)); return r;
}
__device__ __forceinline__ ull add2(ull a, ull b) {
    ull r; asm("add.rn.f32x2 %0, %1, %2;" : "=l"(r) : "l"(a), "l"(b)); return r;
}

// mbarrier wait on phase parity — documented suspend-time form (HW sleep,
// not a hot spin). Mirrors ptx_helpers.cuh MBARRIER_WAIT_PARITY.
__device__ __forceinline__ void mbar_wait(unsigned mb, unsigned phase) {
    unsigned done;
    asm volatile(
        "{\n\t.reg .pred p;\n\t"
        "mbarrier.try_wait.parity.acquire.cta.shared::cta.b64 p, [%1], %2;\n\t"
        "selp.b32 %0, 1, 0, p;\n\t}"
        : "=r"(done) : "r"(mb), "r"(phase) : "memory");
    if (!done) {
        asm volatile(
            "{\n\t.reg .pred P1;\n\t"
            "W_%=:\n\t"
            "mbarrier.try_wait.parity.acquire.cta.shared::cta.b64 P1, [%0], %1, 0x989680;\n\t"
            "@P1 bra D_%=;\n\t"
            "bra.uni W_%=;\n\t"
            "D_%=:\n\t}"
            :: "r"(mb), "r"(phase) : "memory");
    }
}

// q-index into a stage's [512][2][2] twiddle table for element pair (p, p+s).
__device__ __forceinline__ int qidx(int p, int ls) {
    int s = 1 << ls;
    return ((p >> (ls + 1)) << ls) | (p & (s - 1));
}

// Transpose padding 1/8 at float4 granularity: all four access patterns
// (store 8t+e, o2p both sides, read t+128e) conflict-free per 8-lane phase
// (verified by mod-32 bank enumeration at 16B granule).
__device__ __forceinline__ int phys(int p) { return p + (p >> 3); }

// O2 ownership: element index for thread t, slot e.
__device__ __forceinline__ int o2p(int t, int e) {
    return (t & 7) | (e << 3) | ((t >> 3) << 6);
}

static const int NGROUPS_TOTAL = 8192;   // 32768 rows / 4 per group (2 row-pairs)
static const int GRID = 296;             // 148 SMs x 2 CTAs

// dynamic smem layout (86080 B/CTA; 2 CTAs/SM = 168 KB < 228 KB):
//   [0,     36864)  two float4 transpose buffers: [2][1152] float4
//   [36864, 86016)  input staging: 3 buffers x 16384 B (one bulk copy each)
//   [86016, 86040)  3 mbarriers
static const int BUF_F4   = 1152;
static const int XIN_OFF  = 2 * BUF_F4 * 16;        // 36864
static const int MBAR_OFF = XIN_OFF + 3 * 16384;    // 86016
static const int SMEM_DYN = MBAR_OFF + 64;          // 86080

// ---------------- persistent main kernel ----------------
// Stage schedule: O1 intra(1,2,4) -> T1 -> O2 intra(8,16,32) -> one shfl
// stage (64, lane^8) -> T2 -> O3 intra(128,256,512).
// Input staged by ONE cp.async.bulk (16KB contiguous) per group with
// mbarrier completion; float4-packed transposes.
__global__ void __launch_bounds__(128, 2) butterfly_main(
    const float* __restrict__ x,
    const float* __restrict__ tw,       // [10][512][2][2]
    const float* __restrict__ bias,
    float* __restrict__ out)
{
    extern __shared__ char smem_raw[];
    float4* bufT1 = reinterpret_cast<float4*>(smem_raw);               // [1152]
    float4* bufT2 = bufT1 + BUF_F4;                                    // [1152]
    float4* xin   = reinterpret_cast<float4*>(smem_raw + XIN_OFF);     // [3][1024]
    const unsigned mbar_base = (unsigned)__cvta_generic_to_shared(smem_raw + MBAR_OFF);
    const unsigned xin_base  = (unsigned)__cvta_generic_to_shared(smem_raw + XIN_OFF);

    const int t = threadIdx.x;
    const float4* tw4 = reinterpret_cast<const float4*>(tw);  // [10][512] float4

    // ---- one-time twiddle load + repack into registers (160 floats) ----
    float tA[3][4][4];   // O1 stages 1,2,4:    [ls][j][t00,t01,t10,t11]
    float tB[3][4][4];   // O2 stages 8,16,32:  [ls-3][j][t00,t01,t10,t11]
    float tS[8][2];      // shfl stage 64:      [e][ta,tb]
    float tC[3][4][4];   // O3 stages 128..512: [ls-7][j][t00,t01,t10,t11]

    #pragma unroll
    for (int ls = 0; ls < 3; ls++) {
        const int s = 1 << ls;
        #pragma unroll
        for (int j = 0; j < 4; j++) {
            int eL = ((j >> ls) << (ls + 1)) | (j & (s - 1));
            float4 w = tw4[ls * 512 + qidx(8 * t + eL, ls)];
            tA[ls][j][0] = w.x; tA[ls][j][1] = w.y; tA[ls][j][2] = w.z; tA[ls][j][3] = w.w;
        }
    }
    #pragma unroll
    for (int ls = 3; ls < 6; ls++) {
        const int sig = 1 << (ls - 3);
        #pragma unroll
        for (int j = 0; j < 4; j++) {
            int eL = ((j >> (ls - 3)) << (ls - 3 + 1)) | (j & (sig - 1));
            float4 w = tw4[ls * 512 + qidx(o2p(t, eL), ls)];
            tB[ls-3][j][0] = w.x; tB[ls-3][j][1] = w.y; tB[ls-3][j][2] = w.z; tB[ls-3][j][3] = w.w;
        }
    }
    {
        const int i = (t >> 3) & 1;   // bit 6 of o2p = bit 3 of t
        #pragma unroll
        for (int e = 0; e < 8; e++) {
            float4 w = tw4[6 * 512 + qidx(o2p(t, e), 6)];
            tS[e][0] = i ? w.w : w.x;
            tS[e][1] = i ? w.z : w.y;
        }
    }
    #pragma unroll
    for (int ls = 7; ls < 10; ls++) {
        const int sig = 1 << (ls - 7);
        #pragma unroll
        for (int j = 0; j < 4; j++) {
            int eL = ((j >> (ls - 7)) << (ls - 7 + 1)) | (j & (sig - 1));
            float4 w = tw4[ls * 512 + qidx(t + 128 * eL, ls)];
            tC[ls-7][j][0] = w.x; tC[ls-7][j][1] = w.y; tC[ls-7][j][2] = w.z; tC[ls-7][j][3] = w.w;
        }
    }

    // packed bias for O3 ownership p = t + 128e
    ull bv2[8];
    #pragma unroll
    for (int e = 0; e < 8; e++) bv2[e] = bc2(bias[t + 128 * e]);

    // ---- mbarrier init (count=1: only the elected thread arrives) ----
    if (t == 0) {
        #pragma unroll
        for (int b = 0; b < 3; b++)
            asm volatile("mbarrier.init.shared::cta.b64 [%0], 1;"
                         :: "r"(mbar_base + b * 8) : "memory");
    }
    __syncthreads();

    // ---- bulk staging: one 16KB cp.async.bulk per group ----
    auto stage = [&](int gg, int b) {
        if (t == 0 && gg < NGROUPS_TOTAL) {
            unsigned mb = mbar_base + b * 8;
            asm volatile("mbarrier.arrive.expect_tx.shared::cta.b64 _, [%0], %1;"
                         :: "r"(mb), "r"(16384) : "memory");
            asm volatile(
                "cp.async.bulk.shared::cta.global.mbarrier::complete_tx::bytes "
                "[%0], [%1], %2, [%3];"
                :: "r"(xin_base + b * 16384),
                   "l"(x + (size_t)gg * 4096),
                   "r"(16384), "r"(mb) : "memory");
        }
    };

    // ---- prologue: stage first two groups (prefetch distance 2) ----
    const int g0 = blockIdx.x;
    stage(g0, 0);
    stage(g0 + GRID, 1);

    int par = 0, phase = 0;
    for (int g = g0; g < NGROUPS_TOTAL; g += GRID) {
        int nb = par + 2; if (nb >= 3) nb -= 3;
        stage(g + 2 * GRID, nb);

        // wait for this group's bulk copy to land
        mbar_wait(mbar_base + par * 8, phase);

        // input unpack (linear layout: row r at offset r*4KB); O1 ownership
        ull D[2][8];
        #pragma unroll
        for (int c = 0; c < 2; c++) {
            const float4* s0 = &xin[(par * 4 + 2 * c    ) * 256 + 2 * t];
            const float4* s1 = &xin[(par * 4 + 2 * c + 1) * 256 + 2 * t];
            float4 a0 = s0[0], a1 = s0[1];
            float4 b0 = s1[0], b1 = s1[1];
            D[c][0] = pk2(a0.x, b0.x);  D[c][1] = pk2(a0.y, b0.y);
            D[c][2] = pk2(a0.z, b0.z);  D[c][3] = pk2(a0.w, b0.w);
            D[c][4] = pk2(a1.x, b1.x);  D[c][5] = pk2(a1.y, b1.y);
            D[c][6] = pk2(a1.z, b1.z);  D[c][7] = pk2(a1.w, b1.w);
        }
        if (++par >= 3) { par = 0; phase ^= 1; }

        // O1: stages 1,2,4 (intra-thread, e bits 0-2)
        #pragma unroll
        for (int ls = 0; ls < 3; ls++) {
            const int s = 1 << ls;
            #pragma unroll
            for (int j = 0; j < 4; j++) {
                const int eL = ((j >> ls) << (ls + 1)) | (j & (s - 1));
                const int eH = eL + s;
                ull t00 = bc2(tA[ls][j][0]), t01 = bc2(tA[ls][j][1]);
                ull t10 = bc2(tA[ls][j][2]), t11 = bc2(tA[ls][j][3]);
                #pragma unroll
                for (int c = 0; c < 2; c++) {
                    ull x0 = D[c][eL], x1 = D[c][eH];
                    D[c][eL] = fma2(t00, x0, mul2(t01, x1));
                    D[c][eH] = fma2(t10, x0, mul2(t11, x1));
                }
            }
        }

        // ---- transpose 1 (float4-packed: both c streams in one access) ----
        #pragma unroll
        for (int e = 0; e < 8; e++) {
            int p = 8 * t + e;
            float2 v0 = up2(D[0][e]), v1 = up2(D[1][e]);
            bufT1[phys(p)] = make_float4(v0.x, v0.y, v1.x, v1.y);
        }
        __syncthreads();
        #pragma unroll
        for (int e = 0; e < 8; e++) {
            float4 f = bufT1[phys(o2p(t, e))];
            D[0][e] = pk2(f.x, f.y);
            D[1][e] = pk2(f.z, f.w);
        }

        // O2: stages 8,16,32 (intra-thread, e bits = p bits 3-5)
        #pragma unroll
        for (int ls = 3; ls < 6; ls++) {
            const int sig = 1 << (ls - 3);
            #pragma unroll
            for (int j = 0; j < 4; j++) {
                const int eL = ((j >> (ls - 3)) << (ls - 3 + 1)) | (j & (sig - 1));
                const int eH = eL + sig;
                ull t00 = bc2(tB[ls-3][j][0]), t01 = bc2(tB[ls-3][j][1]);
                ull t10 = bc2(tB[ls-3][j][2]), t11 = bc2(tB[ls-3][j][3]);
                #pragma unroll
                for (int c = 0; c < 2; c++) {
                    ull x0 = D[c][eL], x1 = D[c][eH];
                    D[c][eL] = fma2(t00, x0, mul2(t01, x1));
                    D[c][eH] = fma2(t10, x0, mul2(t11, x1));
                }
            }
        }

        // stage 64: ONE shfl stage (p bit 6 = t bit 3 -> lane^8)
        #pragma unroll
        for (int c = 0; c < 2; c++)
            #pragma unroll
            for (int e = 0; e < 8; e++) {
                ull o = __shfl_xor_sync(0xffffffffu, D[c][e], 8);
                D[c][e] = fma2(bc2(tS[e][0]), D[c][e], mul2(bc2(tS[e][1]), o));
            }

        // ---- transpose 2 (float4-packed): O2 -> O3 (p = t + 128e) ----
        #pragma unroll
        for (int e = 0; e < 8; e++) {
            float2 v0 = up2(D[0][e]), v1 = up2(D[1][e]);
            bufT2[phys(o2p(t, e))] = make_float4(v0.x, v0.y, v1.x, v1.y);
        }
        __syncthreads();
        #pragma unroll
        for (int e = 0; e < 8; e++) {
            float4 f = bufT2[phys(t + 128 * e)];
            D[0][e] = pk2(f.x, f.y);
            D[1][e] = pk2(f.z, f.w);
        }

        // O3: stages 128,256,512 (intra-thread, e bits = p bits 7-9)
        #pragma unroll
        for (int ls = 7; ls < 10; ls++) {
            const int sig = 1 << (ls - 7);
            #pragma unroll
            for (int j = 0; j < 4; j++) {
                const int eL = ((j >> (ls - 7)) << (ls - 7 + 1)) | (j & (sig - 1));
                const int eH = eL + sig;
                ull t00 = bc2(tC[ls-7][j][0]), t01 = bc2(tC[ls-7][j][1]);
                ull t10 = bc2(tC[ls-7][j][2]), t11 = bc2(tC[ls-7][j][3]);
                #pragma unroll
                for (int c = 0; c < 2; c++) {
                    ull x0 = D[c][eL], x1 = D[c][eH];
                    D[c][eL] = fma2(t00, x0, mul2(t01, x1));
                    D[c][eH] = fma2(t10, x0, mul2(t11, x1));
                }
            }
        }

        // epilogue: packed bias add + coalesced streaming stores
        #pragma unroll
        for (int c = 0; c < 2; c++) {
            float* o0 = out + (size_t)(g * 4 + 2 * c    ) * 1024;
            float* o1 = out + (size_t)(g * 4 + 2 * c + 1) * 1024;
            #pragma unroll
            for (int e = 0; e < 8; e++) {
                float2 v = up2(add2(D[c][e], bv2[e]));
                int p = t + 128 * e;
                __stcs(o0 + p, v.x);
                __stcs(o1 + p, v.y);
            }
        }
    }
}

extern "C" void kernel_launch(void* const* d_in, const int* in_sizes, int n_in,
                              void* d_out, int out_size) {
    const float* x    = (const float*)d_in[0];   // [32768, 1024]
    const float* tw   = (const float*)d_in[1];   // [1,1,10,512,2,2]
    const float* bias = (const float*)d_in[2];   // [1024]
    float* out = (float*)d_out;

    cudaFuncSetAttribute(butterfly_main,
                         cudaFuncAttributeMaxDynamicSharedMemorySize, SMEM_DYN);
    butterfly_main<<<GRID, 128, SMEM_DYN>>>(x, tw, bias, out);
}